// round 1
// baseline (speedup 1.0000x reference)
#include <cuda_runtime.h>
#include <math.h>

#define SEQ 2048
#define EMB 1024
#define NBQ 256        // algebra blocks
#define NH 16
#define HD 64
#define NBATCH 2
#define NROWS (NBATCH*SEQ)   // 4096

// ---------------- scratch (device globals; no allocation allowed) ----------
__device__ float g_Wq[EMB*EMB];
__device__ float g_Wk[EMB*EMB];
__device__ float g_Wv[EMB*EMB];
__device__ float g_Wo[EMB*EMB];
__device__ float g_Q[NROWS*EMB];
__device__ float g_K[NROWS*EMB];
__device__ float g_V[NROWS*EMB];
__device__ float g_ctx[NROWS*EMB];

// ---------------- weight expansion: quaternion left-mult matrix ------------
// Wbig[in=n*4+j][out=o*4+k] = sum_i W[o,n,i] * C[i,j,k]
__global__ void expand_kernel(const float* __restrict__ W, float* __restrict__ Wbig) {
    int idx = blockIdx.x * blockDim.x + threadIdx.x;
    if (idx >= NBQ * NBQ) return;
    int o = idx / NBQ;
    int n = idx % NBQ;
    const float* w = W + (o * NBQ + n) * 4;
    float w0 = w[0], w1 = w[1], w2 = w[2], w3 = w[3];
    float* base = Wbig + (n * 4) * EMB + o * 4;
    *(float4*)(base + 0 * EMB) = make_float4( w0,  w1,  w2,  w3);
    *(float4*)(base + 1 * EMB) = make_float4(-w1,  w0,  w3, -w2);
    *(float4*)(base + 2 * EMB) = make_float4(-w2, -w3,  w0,  w1);
    *(float4*)(base + 3 * EMB) = make_float4(-w3,  w2, -w1,  w0);
}

// ---------------- SGEMM: C = A[M,K] * B[K,N] + bias[N] ---------------------
#define BM 128
#define BN 128
#define BKK 8
#define TM 8
#define TN 8

__global__ __launch_bounds__(256) void sgemm_bias(
    const float* __restrict__ A, const float* __restrict__ B,
    const float* __restrict__ bias, float* __restrict__ C,
    int M, int N, int K)
{
    __shared__ __align__(16) float As[BKK][BM + 4];
    __shared__ __align__(16) float Bs[BKK][BN];

    int tid = threadIdx.x;
    int bm = blockIdx.y * BM;
    int bn = blockIdx.x * BN;
    int ty = tid / 16;
    int tx = tid % 16;

    int arow = tid / 2;            // 0..127
    int acol = (tid % 2) * 4;      // 0 or 4
    int brow = tid / 32;           // 0..7
    int bcol = (tid % 32) * 4;     // 0..124

    float acc[TM][TN];
#pragma unroll
    for (int i = 0; i < TM; i++)
#pragma unroll
        for (int j = 0; j < TN; j++) acc[i][j] = 0.0f;

    const float* Aptr = A + (bm + arow) * K + acol;
    const float* Bptr = B + brow * N + bn + bcol;

    for (int k0 = 0; k0 < K; k0 += BKK) {
        float4 av = *(const float4*)(Aptr + k0);
        float4 bv = *(const float4*)(Bptr + (long)k0 * N);
        As[acol + 0][arow] = av.x;
        As[acol + 1][arow] = av.y;
        As[acol + 2][arow] = av.z;
        As[acol + 3][arow] = av.w;
        *(float4*)&Bs[brow][bcol] = bv;
        __syncthreads();

#pragma unroll
        for (int k = 0; k < BKK; k++) {
            float4 a0 = *(const float4*)&As[k][ty * 8];
            float4 a1 = *(const float4*)&As[k][ty * 8 + 4];
            float4 b0 = *(const float4*)&Bs[k][tx * 8];
            float4 b1 = *(const float4*)&Bs[k][tx * 8 + 4];
            float af[TM] = {a0.x, a0.y, a0.z, a0.w, a1.x, a1.y, a1.z, a1.w};
            float bf[TN] = {b0.x, b0.y, b0.z, b0.w, b1.x, b1.y, b1.z, b1.w};
#pragma unroll
            for (int i = 0; i < TM; i++)
#pragma unroll
                for (int j = 0; j < TN; j++)
                    acc[i][j] += af[i] * bf[j];
        }
        __syncthreads();
    }

#pragma unroll
    for (int i = 0; i < TM; i++) {
        int row = bm + ty * 8 + i;
        float* crow = C + (long)row * N + bn + tx * 8;
        const float* brow_bias = bias + bn + tx * 8;
#pragma unroll
        for (int jv = 0; jv < 2; jv++) {
            float4 out;
            out.x = acc[i][jv * 4 + 0] + brow_bias[jv * 4 + 0];
            out.y = acc[i][jv * 4 + 1] + brow_bias[jv * 4 + 1];
            out.z = acc[i][jv * 4 + 2] + brow_bias[jv * 4 + 2];
            out.w = acc[i][jv * 4 + 3] + brow_bias[jv * 4 + 3];
            *(float4*)(crow + jv * 4) = out;
        }
    }
}

// ---------------- flash attention (fp32, online softmax) -------------------
#define BQT 64
#define BKV 64
#define KSTR 65   // padded stride for K tile (scalar access)

__global__ __launch_bounds__(256) void flash_attn(
    const float* __restrict__ Q, const float* __restrict__ K,
    const float* __restrict__ V, const int* __restrict__ mask,
    float* __restrict__ ctx)
{
    extern __shared__ __align__(16) float sm[];
    float* Qs = sm;                       // BQT*HD
    float* Ks = Qs + BQT * HD;            // BKV*KSTR
    float* Vs = Ks + BKV * KSTR;          // BKV*HD
    float* Ps = Vs + BKV * HD;            // BQT*BKV

    int tid = threadIdx.x;
    int qt = blockIdx.x;
    int h  = blockIdx.y;
    int b  = blockIdx.z;
    int q0 = qt * BQT;
    int ty = tid / 16;
    int tx = tid % 16;
    const float scale = 0.125f;   // 1/sqrt(64)

    // load Q tile, pre-scaled
    {
        int r  = tid / 4;
        int d0 = (tid % 4) * 16;
        const float* src = Q + ((long)(b * SEQ + q0 + r)) * EMB + h * HD + d0;
#pragma unroll
        for (int i = 0; i < 4; i++) {
            float4 v = *(const float4*)(src + i * 4);
            v.x *= scale; v.y *= scale; v.z *= scale; v.w *= scale;
            *(float4*)(Qs + r * HD + d0 + i * 4) = v;
        }
    }

    float m[4], l[4], o[4][4];
#pragma unroll
    for (int i = 0; i < 4; i++) {
        m[i] = -1e30f; l[i] = 0.0f;
#pragma unroll
        for (int j = 0; j < 4; j++) o[i][j] = 0.0f;
    }

    for (int kt = 0; kt < SEQ / BKV; kt++) {
        __syncthreads();
        // load K (padded-stride scalar layout) and V tiles
        {
            int c  = tid / 4;
            int d0 = (tid % 4) * 16;
            const float* ksrc = K + ((long)(b * SEQ + kt * BKV + c)) * EMB + h * HD + d0;
            const float* vsrc = V + ((long)(b * SEQ + kt * BKV + c)) * EMB + h * HD + d0;
#pragma unroll
            for (int i = 0; i < 4; i++) {
                float4 kv = *(const float4*)(ksrc + i * 4);
                Ks[c * KSTR + d0 + i * 4 + 0] = kv.x;
                Ks[c * KSTR + d0 + i * 4 + 1] = kv.y;
                Ks[c * KSTR + d0 + i * 4 + 2] = kv.z;
                Ks[c * KSTR + d0 + i * 4 + 3] = kv.w;
                float4 vv = *(const float4*)(vsrc + i * 4);
                *(float4*)(Vs + c * HD + d0 + i * 4) = vv;
            }
        }
        __syncthreads();

        // S = Q*K^T fragment
        float s[4][4];
#pragma unroll
        for (int i = 0; i < 4; i++)
#pragma unroll
            for (int j = 0; j < 4; j++) s[i][j] = 0.0f;

#pragma unroll 4
        for (int d = 0; d < HD; d++) {
            float qv[4], kv[4];
#pragma unroll
            for (int i = 0; i < 4; i++) qv[i] = Qs[(ty * 4 + i) * HD + d];
#pragma unroll
            for (int j = 0; j < 4; j++) kv[j] = Ks[(tx * 4 + j) * KSTR + d];
#pragma unroll
            for (int i = 0; i < 4; i++)
#pragma unroll
                for (int j = 0; j < 4; j++)
                    s[i][j] += qv[i] * kv[j];
        }

        // mask
#pragma unroll
        for (int i = 0; i < 4; i++) {
            int mrow = q0 + ty * 4 + i;
            const int* mp = mask + (long)mrow * SEQ + kt * BKV + tx * 4;
#pragma unroll
            for (int j = 0; j < 4; j++)
                if (mp[j] == 0) s[i][j] = -1e30f;
        }

        // online softmax (row groups = 16 lanes sharing ty)
#pragma unroll
        for (int i = 0; i < 4; i++) {
            float mx = fmaxf(fmaxf(s[i][0], s[i][1]), fmaxf(s[i][2], s[i][3]));
#pragma unroll
            for (int off = 1; off < 16; off <<= 1)
                mx = fmaxf(mx, __shfl_xor_sync(0xffffffffu, mx, off, 16));
            float mnew = fmaxf(m[i], mx);
            float f = __expf(m[i] - mnew);
            float rs = 0.0f;
#pragma unroll
            for (int j = 0; j < 4; j++) {
                s[i][j] = __expf(s[i][j] - mnew);
                rs += s[i][j];
            }
#pragma unroll
            for (int off = 1; off < 16; off <<= 1)
                rs += __shfl_xor_sync(0xffffffffu, rs, off, 16);
            l[i] = l[i] * f + rs;
            m[i] = mnew;
#pragma unroll
            for (int j = 0; j < 4; j++) o[i][j] *= f;
        }

        // stage P to smem
#pragma unroll
        for (int i = 0; i < 4; i++)
            *(float4*)(Ps + (ty * 4 + i) * BKV + tx * 4) =
                make_float4(s[i][0], s[i][1], s[i][2], s[i][3]);
        __syncthreads();

        // O += P * V
#pragma unroll 4
        for (int n = 0; n < BKV; n++) {
            float4 vv = *(const float4*)(Vs + n * HD + tx * 4);
            float pv[4];
#pragma unroll
            for (int i = 0; i < 4; i++) pv[i] = Ps[(ty * 4 + i) * BKV + n];
#pragma unroll
            for (int i = 0; i < 4; i++) {
                o[i][0] += pv[i] * vv.x;
                o[i][1] += pv[i] * vv.y;
                o[i][2] += pv[i] * vv.z;
                o[i][3] += pv[i] * vv.w;
            }
        }
    }

    // finalize
#pragma unroll
    for (int i = 0; i < 4; i++) {
        float inv = 1.0f / l[i];
        int r = q0 + ty * 4 + i;
        float4 out = make_float4(o[i][0] * inv, o[i][1] * inv,
                                 o[i][2] * inv, o[i][3] * inv);
        *(float4*)(ctx + ((long)(b * SEQ + r)) * EMB + h * HD + tx * 4) = out;
    }
}

// ---------------- launch ----------------------------------------------------
extern "C" void kernel_launch(void* const* d_in, const int* in_sizes, int n_in,
                              void* d_out, int out_size)
{
    const float* x    = (const float*)d_in[0];
    const int*   mask = (const int*)  d_in[1];
    const float* Wq   = (const float*)d_in[2];
    const float* bq   = (const float*)d_in[3];
    const float* Wk   = (const float*)d_in[4];
    const float* bk   = (const float*)d_in[5];
    const float* Wv   = (const float*)d_in[6];
    const float* bv   = (const float*)d_in[7];
    const float* Wo   = (const float*)d_in[8];
    const float* bo   = (const float*)d_in[9];
    float* out = (float*)d_out;

    float *pWq, *pWk, *pWv, *pWo, *pQ, *pK, *pV, *pCtx;
    cudaGetSymbolAddress((void**)&pWq, g_Wq);
    cudaGetSymbolAddress((void**)&pWk, g_Wk);
    cudaGetSymbolAddress((void**)&pWv, g_Wv);
    cudaGetSymbolAddress((void**)&pWo, g_Wo);
    cudaGetSymbolAddress((void**)&pQ,  g_Q);
    cudaGetSymbolAddress((void**)&pK,  g_K);
    cudaGetSymbolAddress((void**)&pV,  g_V);
    cudaGetSymbolAddress((void**)&pCtx, g_ctx);

    const int flash_smem = (BQT*HD + BKV*KSTR + BKV*HD + BQT*BKV) * (int)sizeof(float);
    cudaFuncSetAttribute(flash_attn, cudaFuncAttributeMaxDynamicSharedMemorySize, flash_smem);

    // 1. expand quaternion weights to dense 1024x1024 matrices
    expand_kernel<<<NBQ*NBQ/256, 256>>>(Wq, pWq);
    expand_kernel<<<NBQ*NBQ/256, 256>>>(Wk, pWk);
    expand_kernel<<<NBQ*NBQ/256, 256>>>(Wv, pWv);
    expand_kernel<<<NBQ*NBQ/256, 256>>>(Wo, pWo);

    // 2. Q/K/V projections
    dim3 ggrid(EMB / BN, NROWS / BM);
    sgemm_bias<<<ggrid, 256>>>(x, pWq, bq, pQ, NROWS, EMB, EMB);
    sgemm_bias<<<ggrid, 256>>>(x, pWk, bk, pK, NROWS, EMB, EMB);
    sgemm_bias<<<ggrid, 256>>>(x, pWv, bv, pV, NROWS, EMB, EMB);

    // 3. attention
    dim3 agrid(SEQ / BQT, NH, NBATCH);
    flash_attn<<<agrid, 256, flash_smem>>>(pQ, pK, pV, mask, pCtx);

    // 4. output projection straight into d_out
    sgemm_bias<<<ggrid, 256>>>(pCtx, pWo, bo, out, NROWS, EMB, EMB);
}

// round 3
// speedup vs baseline: 3.1603x; 3.1603x over previous
#include <cuda_runtime.h>
#include <math.h>

#define SEQ 2048
#define EMB 1024
#define NBQ 256
#define NH 16
#define HD 64
#define NBATCH 2
#define NROWS (NBATCH*SEQ)   // 4096

// ---------------- scratch (device globals) ---------------------------------
__device__ float g_Wq[EMB*EMB];
__device__ float g_Wk[EMB*EMB];
__device__ float g_Wv[EMB*EMB];
__device__ float g_Wo[EMB*EMB];
__device__ float g_Q[NROWS*EMB];
__device__ float g_K[NROWS*EMB];
__device__ float g_V[NROWS*EMB];
__device__ float g_ctx[NROWS*EMB];
__device__ int   g_msum[(SEQ/64)*(SEQ/64)];

// ---------------- helpers ---------------------------------------------------
__device__ __forceinline__ unsigned f2tf32(float x) {
    unsigned u;
    asm("cvt.rna.tf32.f32 %0, %1;" : "=r"(u) : "f"(x));
    return u;
}
__device__ __forceinline__ float tf32f(float x) { return __uint_as_float(f2tf32(x)); }

__device__ __forceinline__ void mma_tf32(float* d, const unsigned* a, const unsigned* b) {
    asm volatile(
        "mma.sync.aligned.m16n8k8.row.col.f32.tf32.tf32.f32 "
        "{%0,%1,%2,%3},{%4,%5,%6,%7},{%8,%9},{%0,%1,%2,%3};"
        : "+f"(d[0]), "+f"(d[1]), "+f"(d[2]), "+f"(d[3])
        : "r"(a[0]), "r"(a[1]), "r"(a[2]), "r"(a[3]), "r"(b[0]), "r"(b[1]));
}

// ---------------- weight expansion (quaternion left-mult) ------------------
__global__ void expand_kernel(const float* __restrict__ W, float* __restrict__ Wbig) {
    int idx = blockIdx.x * blockDim.x + threadIdx.x;
    if (idx >= NBQ * NBQ) return;
    int o = idx / NBQ;
    int n = idx % NBQ;
    const float* w = W + (o * NBQ + n) * 4;
    float w0 = w[0], w1 = w[1], w2 = w[2], w3 = w[3];
    float* base = Wbig + (n * 4) * EMB + o * 4;
    *(float4*)(base + 0 * EMB) = make_float4( w0,  w1,  w2,  w3);
    *(float4*)(base + 1 * EMB) = make_float4(-w1,  w0,  w3, -w2);
    *(float4*)(base + 2 * EMB) = make_float4(-w2, -w3,  w0,  w1);
    *(float4*)(base + 3 * EMB) = make_float4(-w3,  w2, -w1,  w0);
}

// ---------------- mask tile summary ----------------------------------------
__global__ void mask_summary(const int* __restrict__ mask, int* __restrict__ sum) {
    int tile = blockIdx.x;                 // qt*32 + kt
    int qt = tile / (SEQ/64), kt = tile % (SEQ/64);
    int tid = threadIdx.x;
    int ok = 1;
    for (int i = tid; i < 64*64; i += 256) {
        int r = i / 64, c = i % 64;
        ok &= (mask[(qt*64 + r) * SEQ + kt*64 + c] != 0);
    }
    int allok = __syncthreads_and(ok);
    if (tid == 0) sum[tile] = allok;
}

// ---------------- TF32 tensor-core GEMM ------------------------------------
// C[z] = A[M=4096,K=1024] * W[z][K,N=1024] + bias[z],  z = blockIdx.z
#define ASTR 36
#define BSTR 136

struct GemmArgs {
    const float* A;
    const float* W[3];
    const float* bias[3];
    float* out[3];
};

__global__ __launch_bounds__(256) void gemm_tf32(GemmArgs ga) {
    __shared__ float As[128 * ASTR];
    __shared__ float Bs[32 * BSTR];

    int tid = threadIdx.x;
    int z = blockIdx.z;
    const float* A = ga.A;
    const float* W = ga.W[z];
    const float* bias = ga.bias[z];
    float* C = ga.out[z];

    int bm = blockIdx.y * 128;
    int bn = blockIdx.x * 128;
    int warp = tid / 32, lane = tid % 32;
    int gid = lane >> 2, tig = lane & 3;
    int wm = (warp / 4) * 64, wn = (warp % 4) * 32;

    int arow = tid / 8;          // rows arow + i*32
    int acol = (tid % 8) * 4;
    int brow = tid / 32;         // rows brow + i*8
    int bcol = (tid % 32) * 4;

    float acc[4][4][4];
#pragma unroll
    for (int mt = 0; mt < 4; mt++)
#pragma unroll
        for (int nt = 0; nt < 4; nt++)
#pragma unroll
            for (int r = 0; r < 4; r++) acc[mt][nt][r] = 0.0f;

    float4 pa[4], pb[4];

#define LOADG(k0)                                                              \
    {                                                                          \
        _Pragma("unroll")                                                      \
        for (int i = 0; i < 4; i++)                                            \
            pa[i] = *(const float4*)(A + (long)(bm + arow + i*32) * EMB + (k0) + acol); \
        _Pragma("unroll")                                                      \
        for (int i = 0; i < 4; i++)                                            \
            pb[i] = *(const float4*)(W + (long)((k0) + brow + i*8) * EMB + bn + bcol);  \
    }
#define STORES()                                                               \
    {                                                                          \
        _Pragma("unroll")                                                      \
        for (int i = 0; i < 4; i++) {                                          \
            int r = arow + i*32;                                               \
            As[r*ASTR + acol + 0] = tf32f(pa[i].x);                            \
            As[r*ASTR + acol + 1] = tf32f(pa[i].y);                            \
            As[r*ASTR + acol + 2] = tf32f(pa[i].z);                            \
            As[r*ASTR + acol + 3] = tf32f(pa[i].w);                            \
        }                                                                      \
        _Pragma("unroll")                                                      \
        for (int i = 0; i < 4; i++) {                                          \
            int r = brow + i*8;                                                \
            Bs[r*BSTR + bcol + 0] = tf32f(pb[i].x);                            \
            Bs[r*BSTR + bcol + 1] = tf32f(pb[i].y);                            \
            Bs[r*BSTR + bcol + 2] = tf32f(pb[i].z);                            \
            Bs[r*BSTR + bcol + 3] = tf32f(pb[i].w);                            \
        }                                                                      \
    }

    LOADG(0);
    STORES();
    __syncthreads();

    for (int kt = 0; kt < EMB / 32; kt++) {
        if (kt + 1 < EMB / 32) LOADG((kt + 1) * 32);

#pragma unroll
        for (int ks = 0; ks < 4; ks++) {
            int k0 = ks * 8;
            unsigned af[4][4], bf[4][2];
#pragma unroll
            for (int mt = 0; mt < 4; mt++) {
                int r0 = wm + mt * 16;
                af[mt][0] = __float_as_uint(As[(r0 + gid)     * ASTR + k0 + tig]);
                af[mt][1] = __float_as_uint(As[(r0 + gid + 8) * ASTR + k0 + tig]);
                af[mt][2] = __float_as_uint(As[(r0 + gid)     * ASTR + k0 + tig + 4]);
                af[mt][3] = __float_as_uint(As[(r0 + gid + 8) * ASTR + k0 + tig + 4]);
            }
#pragma unroll
            for (int nt = 0; nt < 4; nt++) {
                int c0 = wn + nt * 8;
                bf[nt][0] = __float_as_uint(Bs[(k0 + tig)     * BSTR + c0 + gid]);
                bf[nt][1] = __float_as_uint(Bs[(k0 + tig + 4) * BSTR + c0 + gid]);
            }
#pragma unroll
            for (int mt = 0; mt < 4; mt++)
#pragma unroll
                for (int nt = 0; nt < 4; nt++)
                    mma_tf32(acc[mt][nt], af[mt], bf[nt]);
        }
        __syncthreads();
        if (kt + 1 < EMB / 32) {
            STORES();
            __syncthreads();
        }
    }

#pragma unroll
    for (int mt = 0; mt < 4; mt++)
#pragma unroll
        for (int nt = 0; nt < 4; nt++) {
            int gm = bm + wm + mt * 16 + gid;
            int gn = bn + wn + nt * 8 + tig * 2;
            float b0 = bias[gn], b1 = bias[gn + 1];
            float2 r0 = make_float2(acc[mt][nt][0] + b0, acc[mt][nt][1] + b1);
            float2 r1 = make_float2(acc[mt][nt][2] + b0, acc[mt][nt][3] + b1);
            *(float2*)(C + (long)gm * EMB + gn) = r0;
            *(float2*)(C + (long)(gm + 8) * EMB + gn) = r1;
        }
}

// ---------------- TF32 flash attention -------------------------------------
#define QSTR 68
#define VSTR 72
#define PSTR 72

__global__ __launch_bounds__(128) void flash_tf32(
    const float* __restrict__ Q, const float* __restrict__ K,
    const float* __restrict__ V, const int* __restrict__ mask,
    const int* __restrict__ msum, float* __restrict__ ctx)
{
    extern __shared__ float fs[];
    float* Qs = fs;                       // 64*QSTR
    float* Ks = Qs + 64 * QSTR;           // 64*QSTR
    float* Vs = Ks + 64 * QSTR;           // 64*VSTR
    float* Ps = Vs + 64 * VSTR;           // 4*16*PSTR

    int tid = threadIdx.x;
    int w = tid / 32, lane = tid % 32;
    int gid = lane >> 2, tig = lane & 3;
    int qt = blockIdx.x, h = blockIdx.y, b = blockIdx.z;
    int q0 = qt * 64;
    const float scale = 0.125f;

    // load Q tile (pre-scaled, tf32-rounded)
    {
        int colf4 = (tid % 16) * 4;
#pragma unroll
        for (int i = 0; i < 8; i++) {
            int row = tid / 16 + i * 8;
            const float* src = Q + (long)(b * SEQ + q0 + row) * EMB + h * HD + colf4;
            float4 v = *(const float4*)src;
            Qs[row * QSTR + colf4 + 0] = tf32f(v.x * scale);
            Qs[row * QSTR + colf4 + 1] = tf32f(v.y * scale);
            Qs[row * QSTR + colf4 + 2] = tf32f(v.z * scale);
            Qs[row * QSTR + colf4 + 3] = tf32f(v.w * scale);
        }
    }
    __syncthreads();

    // hoist Q fragments (constant across kv tiles)
    unsigned aq[8][4];
#pragma unroll
    for (int ks = 0; ks < 8; ks++) {
        int r0 = w * 16;
        int k0 = ks * 8;
        aq[ks][0] = __float_as_uint(Qs[(r0 + gid)     * QSTR + k0 + tig]);
        aq[ks][1] = __float_as_uint(Qs[(r0 + gid + 8) * QSTR + k0 + tig]);
        aq[ks][2] = __float_as_uint(Qs[(r0 + gid)     * QSTR + k0 + tig + 4]);
        aq[ks][3] = __float_as_uint(Qs[(r0 + gid + 8) * QSTR + k0 + tig + 4]);
    }

    float o[8][4];
#pragma unroll
    for (int dt = 0; dt < 8; dt++)
#pragma unroll
        for (int r = 0; r < 4; r++) o[dt][r] = 0.0f;
    float mA = -1e30f, mB = -1e30f, lA = 0.0f, lB = 0.0f;

    for (int kt = 0; kt < SEQ / 64; kt++) {
        __syncthreads();   // previous PV reads of Vs done
        // load K/V tiles
        {
            int colf4 = (tid % 16) * 4;
#pragma unroll
            for (int i = 0; i < 8; i++) {
                int row = tid / 16 + i * 8;
                long gr = (long)(b * SEQ + kt * 64 + row) * EMB + h * HD + colf4;
                float4 kv = *(const float4*)(K + gr);
                Ks[row * QSTR + colf4 + 0] = tf32f(kv.x);
                Ks[row * QSTR + colf4 + 1] = tf32f(kv.y);
                Ks[row * QSTR + colf4 + 2] = tf32f(kv.z);
                Ks[row * QSTR + colf4 + 3] = tf32f(kv.w);
                float4 vv = *(const float4*)(V + gr);
                Vs[row * VSTR + colf4 + 0] = tf32f(vv.x);
                Vs[row * VSTR + colf4 + 1] = tf32f(vv.y);
                Vs[row * VSTR + colf4 + 2] = tf32f(vv.z);
                Vs[row * VSTR + colf4 + 3] = tf32f(vv.w);
            }
        }
        __syncthreads();

        // S = Q K^T
        float s[8][4];
#pragma unroll
        for (int nt = 0; nt < 8; nt++) {
            s[nt][0] = s[nt][1] = s[nt][2] = s[nt][3] = 0.0f;
#pragma unroll
            for (int ks = 0; ks < 8; ks++) {
                int k0 = ks * 8;
                unsigned bk[2];
                bk[0] = __float_as_uint(Ks[(nt * 8 + gid) * QSTR + k0 + tig]);
                bk[1] = __float_as_uint(Ks[(nt * 8 + gid) * QSTR + k0 + tig + 4]);
                mma_tf32(s[nt], aq[ks], bk);
            }
        }

        // mask (only when tile contains zeros)
        if (!msum[qt * (SEQ/64) + kt]) {
            int qrA = q0 + w * 16 + gid;
            int qrB = qrA + 8;
#pragma unroll
            for (int nt = 0; nt < 8; nt++) {
                int kc = kt * 64 + nt * 8 + tig * 2;
                const int* mpA = mask + (long)qrA * SEQ + kc;
                const int* mpB = mask + (long)qrB * SEQ + kc;
                if (mpA[0] == 0) s[nt][0] = -1e30f;
                if (mpA[1] == 0) s[nt][1] = -1e30f;
                if (mpB[0] == 0) s[nt][2] = -1e30f;
                if (mpB[1] == 0) s[nt][3] = -1e30f;
            }
        }

        // online softmax (two rows per thread: gid / gid+8)
        float mxA = -1e30f, mxB = -1e30f;
#pragma unroll
        for (int nt = 0; nt < 8; nt++) {
            mxA = fmaxf(mxA, fmaxf(s[nt][0], s[nt][1]));
            mxB = fmaxf(mxB, fmaxf(s[nt][2], s[nt][3]));
        }
#pragma unroll
        for (int off = 1; off < 4; off <<= 1) {
            mxA = fmaxf(mxA, __shfl_xor_sync(0xffffffffu, mxA, off));
            mxB = fmaxf(mxB, __shfl_xor_sync(0xffffffffu, mxB, off));
        }
        float mnA = fmaxf(mA, mxA), mnB = fmaxf(mB, mxB);
        float fA = __expf(mA - mnA), fB = __expf(mB - mnB);
        mA = mnA; mB = mnB;
        float sumA = 0.0f, sumB = 0.0f;
#pragma unroll
        for (int nt = 0; nt < 8; nt++) {
            s[nt][0] = __expf(s[nt][0] - mA);
            s[nt][1] = __expf(s[nt][1] - mA);
            s[nt][2] = __expf(s[nt][2] - mB);
            s[nt][3] = __expf(s[nt][3] - mB);
            sumA += s[nt][0] + s[nt][1];
            sumB += s[nt][2] + s[nt][3];
        }
#pragma unroll
        for (int off = 1; off < 4; off <<= 1) {
            sumA += __shfl_xor_sync(0xffffffffu, sumA, off);
            sumB += __shfl_xor_sync(0xffffffffu, sumB, off);
        }
        lA = lA * fA + sumA;
        lB = lB * fB + sumB;
#pragma unroll
        for (int dt = 0; dt < 8; dt++) {
            o[dt][0] *= fA; o[dt][1] *= fA;
            o[dt][2] *= fB; o[dt][3] *= fB;
        }

        // stage P (tf32) to per-warp smem
        float* pw = Ps + w * 16 * PSTR;
#pragma unroll
        for (int nt = 0; nt < 8; nt++) {
            int c = nt * 8 + tig * 2;
            pw[gid * PSTR + c]           = tf32f(s[nt][0]);
            pw[gid * PSTR + c + 1]       = tf32f(s[nt][1]);
            pw[(gid + 8) * PSTR + c]     = tf32f(s[nt][2]);
            pw[(gid + 8) * PSTR + c + 1] = tf32f(s[nt][3]);
        }
        __syncwarp();

        // O += P V
#pragma unroll
        for (int ks = 0; ks < 8; ks++) {
            int k0 = ks * 8;
            unsigned ap[4];
            ap[0] = __float_as_uint(pw[gid * PSTR + k0 + tig]);
            ap[1] = __float_as_uint(pw[(gid + 8) * PSTR + k0 + tig]);
            ap[2] = __float_as_uint(pw[gid * PSTR + k0 + tig + 4]);
            ap[3] = __float_as_uint(pw[(gid + 8) * PSTR + k0 + tig + 4]);
#pragma unroll
            for (int dt = 0; dt < 8; dt++) {
                unsigned bv[2];
                bv[0] = __float_as_uint(Vs[(k0 + tig)     * VSTR + dt * 8 + gid]);
                bv[1] = __float_as_uint(Vs[(k0 + tig + 4) * VSTR + dt * 8 + gid]);
                mma_tf32(o[dt], ap, bv);
            }
        }
        __syncwarp();
    }

    // finalize
    float invA = 1.0f / lA, invB = 1.0f / lB;
    long rowA = (long)(b * SEQ + q0 + w * 16 + gid) * EMB;
    long rowB = rowA + 8L * EMB;
#pragma unroll
    for (int dt = 0; dt < 8; dt++) {
        int gn = h * HD + dt * 8 + tig * 2;
        *(float2*)(ctx + rowA + gn) = make_float2(o[dt][0] * invA, o[dt][1] * invA);
        *(float2*)(ctx + rowB + gn) = make_float2(o[dt][2] * invB, o[dt][3] * invB);
    }
}

// ---------------- launch ----------------------------------------------------
extern "C" void kernel_launch(void* const* d_in, const int* in_sizes, int n_in,
                              void* d_out, int out_size)
{
    const float* x    = (const float*)d_in[0];
    const int*   mask = (const int*)  d_in[1];
    const float* Wq   = (const float*)d_in[2];
    const float* bq   = (const float*)d_in[3];
    const float* Wk   = (const float*)d_in[4];
    const float* bk   = (const float*)d_in[5];
    const float* Wv   = (const float*)d_in[6];
    const float* bv   = (const float*)d_in[7];
    const float* Wo   = (const float*)d_in[8];
    const float* bo   = (const float*)d_in[9];
    float* out = (float*)d_out;

    float *pWq, *pWk, *pWv, *pWo, *pQ, *pK, *pV, *pCtx;
    int* pMsum;
    cudaGetSymbolAddress((void**)&pWq, g_Wq);
    cudaGetSymbolAddress((void**)&pWk, g_Wk);
    cudaGetSymbolAddress((void**)&pWv, g_Wv);
    cudaGetSymbolAddress((void**)&pWo, g_Wo);
    cudaGetSymbolAddress((void**)&pQ,  g_Q);
    cudaGetSymbolAddress((void**)&pK,  g_K);
    cudaGetSymbolAddress((void**)&pV,  g_V);
    cudaGetSymbolAddress((void**)&pCtx, g_ctx);
    cudaGetSymbolAddress((void**)&pMsum, g_msum);

    const int flash_smem = (64*QSTR*2 + 64*VSTR + 4*16*PSTR) * (int)sizeof(float);
    cudaFuncSetAttribute(flash_tf32, cudaFuncAttributeMaxDynamicSharedMemorySize, flash_smem);

    // 1. expand quaternion weights + mask tile summary
    expand_kernel<<<NBQ*NBQ/256, 256>>>(Wq, pWq);
    expand_kernel<<<NBQ*NBQ/256, 256>>>(Wk, pWk);
    expand_kernel<<<NBQ*NBQ/256, 256>>>(Wv, pWv);
    expand_kernel<<<NBQ*NBQ/256, 256>>>(Wo, pWo);
    mask_summary<<<(SEQ/64)*(SEQ/64), 256>>>(mask, pMsum);

    // 2. fused Q/K/V projections (z = 0,1,2)
    GemmArgs qkv;
    qkv.A = x;
    qkv.W[0] = pWq; qkv.W[1] = pWk; qkv.W[2] = pWv;
    qkv.bias[0] = bq; qkv.bias[1] = bk; qkv.bias[2] = bv;
    qkv.out[0] = pQ; qkv.out[1] = pK; qkv.out[2] = pV;
    dim3 ggrid(EMB/128, NROWS/128, 3);
    gemm_tf32<<<ggrid, 256>>>(qkv);

    // 3. attention
    dim3 agrid(SEQ/64, NH, NBATCH);
    flash_tf32<<<agrid, 128, flash_smem>>>(pQ, pK, pV, mask, pMsum, pCtx);

    // 4. output projection -> d_out
    GemmArgs og;
    og.A = pCtx;
    og.W[0] = pWo; og.W[1] = pWo; og.W[2] = pWo;
    og.bias[0] = bo; og.bias[1] = bo; og.bias[2] = bo;
    og.out[0] = out; og.out[1] = out; og.out[2] = out;
    dim3 ogrid(EMB/128, NROWS/128, 1);
    gemm_tf32<<<ogrid, 256>>>(og);
}